// round 16
// baseline (speedup 1.0000x reference)
#include <cuda_runtime.h>
#include <cuda_fp16.h>
#include <math.h>
#include <stdint.h>

// Problem constants
constexpr int Bc  = 2;
constexpr int Sc  = 2048;
constexpr int Dc  = 2048;
constexpr int Hc  = 16;
constexpr int DHc = 128;
constexpr int Mc  = Bc * Sc;   // 4096 rows for projections

// ---------------------------------------------------------------------------
// Scratch (device globals: allocation-free per harness rules)
// ---------------------------------------------------------------------------
__device__ __half g_Vh [(size_t)Mc * Dc];      // half V
__device__ __half g_xh [(size_t)Mc * Dc];
__device__ __half g_Qh [(size_t)Mc * Dc];      // roped + (scale*log2e)-scaled
__device__ __half g_Kh [(size_t)Mc * Dc];      // roped
__device__ __half g_Ah [(size_t)Mc * Dc];      // attention out (half)
__device__ __half g_wqh[(size_t)Dc * Dc];
__device__ __half g_wkh[(size_t)Dc * Dc];
__device__ __half g_wvh[(size_t)Dc * Dc];
__device__ __half g_woh[(size_t)Dc * Dc];

#define CP_ASYNC16(dst, src) \
    asm volatile("cp.async.cg.shared.global [%0], [%1], 16;\n" :: "r"(dst), "l"(src))

#define MMA_F16(c, a0, a1, a2, a3, b0, b1)                                     \
    asm volatile(                                                              \
        "mma.sync.aligned.m16n8k16.row.col.f32.f16.f16.f32 "                   \
        "{%0,%1,%2,%3}, {%4,%5,%6,%7}, {%8,%9}, {%0,%1,%2,%3};\n"              \
        : "+f"((c)[0]), "+f"((c)[1]), "+f"((c)[2]), "+f"((c)[3])               \
        : "r"(a0), "r"(a1), "r"(a2), "r"(a3), "r"(b0), "r"(b1))

#define LDSM_X4(r0, r1, r2, r3, addr)                                          \
    asm volatile("ldmatrix.sync.aligned.m8n8.x4.shared.b16 {%0,%1,%2,%3}, [%4];" \
        : "=r"(r0), "=r"(r1), "=r"(r2), "=r"(r3) : "r"(addr))

#define LDSM_X4_T(r0, r1, r2, r3, addr)                                        \
    asm volatile("ldmatrix.sync.aligned.m8n8.x4.trans.shared.b16 {%0,%1,%2,%3}, [%4];" \
        : "=r"(r0), "=r"(r1), "=r"(r2), "=r"(r3) : "r"(addr))

// 16B-granular XOR swizzles (byte offsets). Row widths: 16 segs (QKV), 8 (P).
__device__ __forceinline__ uint32_t swz16(int row, int seg) {
    return (uint32_t)((row * 16 + (seg ^ (row & 7))) << 4);
}
__device__ __forceinline__ uint32_t swz8(int row, int seg) {
    return (uint32_t)((row * 8 + (seg ^ (row & 7))) << 4);
}

// ---------------------------------------------------------------------------
// fp32 -> fp16: all five inputs, one launch. 4 independent float4 loads per
// thread (MLP=4) arranged as 2 adjacent pairs -> 2 uint4 (16B) stores.
// y<4: weights; y=4,5: x halves. n4 (=1048576) divisible by 1024 exactly.
// ---------------------------------------------------------------------------
__global__ void cvt_all(const float* __restrict__ x,
                        const float* __restrict__ w0, const float* __restrict__ w1,
                        const float* __restrict__ w2, const float* __restrict__ w3,
                        __half* __restrict__ xh,
                        __half* __restrict__ o0, __half* __restrict__ o1,
                        __half* __restrict__ o2, __half* __restrict__ o3, int n4) {
    const float* in;
    __half* out;
    switch (blockIdx.y) {
        case 0:  in = w0; out = o0; break;
        case 1:  in = w1; out = o1; break;
        case 2:  in = w2; out = o2; break;
        case 3:  in = w3; out = o3; break;
        case 4:  in = x;                     out = xh;                     break;
        default: in = x + (size_t)n4 * 4;    out = xh + (size_t)n4 * 4;    break;
    }
    const int base = blockIdx.x * 1024 + threadIdx.x * 2;
    float4 v0 = *(const float4*)(in + (size_t)base * 4);
    float4 v1 = *(const float4*)(in + (size_t)(base + 1) * 4);
    float4 v2 = *(const float4*)(in + (size_t)(base + 512) * 4);
    float4 v3 = *(const float4*)(in + (size_t)(base + 513) * 4);

    uint4 u0, u1;
    __half2 h;
    h = __floats2half2_rn(v0.x, v0.y); u0.x = *(uint32_t*)&h;
    h = __floats2half2_rn(v0.z, v0.w); u0.y = *(uint32_t*)&h;
    h = __floats2half2_rn(v1.x, v1.y); u0.z = *(uint32_t*)&h;
    h = __floats2half2_rn(v1.z, v1.w); u0.w = *(uint32_t*)&h;
    h = __floats2half2_rn(v2.x, v2.y); u1.x = *(uint32_t*)&h;
    h = __floats2half2_rn(v2.z, v2.w); u1.y = *(uint32_t*)&h;
    h = __floats2half2_rn(v3.x, v3.y); u1.z = *(uint32_t*)&h;
    h = __floats2half2_rn(v3.z, v3.w); u1.w = *(uint32_t*)&h;

    *(uint4*)(out + (size_t)base * 4)         = u0;
    *(uint4*)(out + (size_t)(base + 512) * 4) = u1;
}

// ---------------------------------------------------------------------------
// Shared GEMM constants
// ---------------------------------------------------------------------------
constexpr int HST = 40;                          // halves per smem row
constexpr int QKV_STG_H = 256 * HST;             // stage: A 128 + B 128 rows
constexpr int GEMM_SMEM_B = 3 * QKV_STG_H * 2;   // 61440 bytes (3-stage)
constexpr int GO_STG_H = 192 * HST;              // stage: A 64 + B 128 rows
constexpr int GO_SMEM_B = 3 * GO_STG_H * 2;      // 46080 bytes (3-stage)

// ---------------------------------------------------------------------------
// Fused QKV projection: BM=BN=128, BK=32, 128 thr, 3-stage cp.async pipeline
// (loads issued after the barrier into stage (kt+2)%3 — race-free).
// z selects W/output; z<2 fuses RoPE (+ Q scale with log2e folded in).
// ---------------------------------------------------------------------------
__global__ void __launch_bounds__(128, 3) gemm_qkv(
    const __half* __restrict__ A,
    const __half* __restrict__ Bq, const __half* __restrict__ Bk,
    const __half* __restrict__ Bv,
    __half* __restrict__ Qh, __half* __restrict__ Kh, __half* __restrict__ Vh,
    const float* __restrict__ cosp, const float* __restrict__ sinp) {
    extern __shared__ __half hsm[];

    const int z = blockIdx.z;
    const __half* B = (z == 0) ? Bq : ((z == 1) ? Bk : Bv);
    const int K = Dc, N = Dc;

    const int tid  = threadIdx.x;
    const int wid  = tid >> 5;
    const int lane = tid & 31;
    const int wm = (wid & 1) * 64;
    const int wn = (wid >> 1) * 64;
    const int gp = lane >> 2;
    const int t4 = lane & 3;
    const int m0 = blockIdx.y * 128;
    const int n0 = blockIdx.x * 128;

    const int arow = (lane & 7) + ((lane >> 3) & 1) * 8;
    const int acol = (lane >> 4) * 8;
    const int brow = (lane & 7) + (lane >> 4) * 8;
    const int bcol = ((lane >> 3) & 1) * 8;

    const int lrow = tid >> 2;
    const int lseg = tid & 3;
    const __half* Ag = A + (size_t)(m0 + lrow) * K + lseg * 8;
    const __half* Bg = B + (size_t)(n0 + lrow) * K + lseg * 8;

    const uint32_t sS_u = (uint32_t)__cvta_generic_to_shared(hsm);

    auto load_st = [&](int st, int k0) {
        uint32_t bA = sS_u + (uint32_t)(st * QKV_STG_H * 2);
        uint32_t bB = bA + (uint32_t)(128 * HST * 2);
#pragma unroll
        for (int p = 0; p < 4; p++) {
            int row = lrow + p * 32;
            CP_ASYNC16(bA + (uint32_t)((row * HST + lseg * 8) * 2),
                       Ag + (size_t)p * 32 * K + k0);
            CP_ASYNC16(bB + (uint32_t)((row * HST + lseg * 8) * 2),
                       Bg + (size_t)p * 32 * K + k0);
        }
        asm volatile("cp.async.commit_group;\n");
    };

    float acc[4][8][4];
#pragma unroll
    for (int im = 0; im < 4; im++)
#pragma unroll
        for (int in_ = 0; in_ < 8; in_++)
#pragma unroll
            for (int r = 0; r < 4; r++) acc[im][in_][r] = 0.f;

    const int nt = K / 32;

    load_st(0, 0);
    load_st(1, 32);

    int cs = 0, ld = 2;
    for (int kt = 0; kt < nt; kt++) {
        if (kt + 1 < nt) asm volatile("cp.async.wait_group 1;\n");
        else             asm volatile("cp.async.wait_group 0;\n");
        __syncthreads();

        if (kt + 2 < nt) {
            load_st(ld, (kt + 2) * 32);
            ld = (ld == 2) ? 0 : ld + 1;
        }

        const uint32_t cA_u = sS_u + (uint32_t)(cs * QKV_STG_H * 2);
        const uint32_t cB_u = cA_u + (uint32_t)(128 * HST * 2);
        cs = (cs == 2) ? 0 : cs + 1;

#pragma unroll
        for (int ks = 0; ks < 2; ks++) {
            const int kk = ks * 16;
            uint32_t af[4][4];
#pragma unroll
            for (int im = 0; im < 4; im++)
                LDSM_X4(af[im][0], af[im][1], af[im][2], af[im][3],
                        cA_u + (uint32_t)(((wm + im * 16 + arow) * HST + kk + acol) * 2));
            uint32_t bf[8][2];
#pragma unroll
            for (int j2 = 0; j2 < 4; j2++)
                LDSM_X4(bf[2 * j2][0], bf[2 * j2][1],
                        bf[2 * j2 + 1][0], bf[2 * j2 + 1][1],
                        cB_u + (uint32_t)(((wn + j2 * 16 + brow) * HST + kk + bcol) * 2));
#pragma unroll
            for (int im = 0; im < 4; im++)
#pragma unroll
                for (int in_ = 0; in_ < 8; in_++)
                    MMA_F16(acc[im][in_], af[im][0], af[im][1], af[im][2],
                            af[im][3], bf[in_][0], bf[in_][1]);
        }
    }
    __syncthreads();   // done with smem before epilogue reuses it

    if (z == 2) {
#pragma unroll
        for (int im = 0; im < 4; im++) {
            const int mA = m0 + wm + im * 16 + gp;
#pragma unroll
            for (int in_ = 0; in_ < 8; in_++) {
                const int n = n0 + wn + in_ * 8 + 2 * t4;
                *(__half2*)(Vh + (size_t)mA * N + n) =
                    __floats2half2_rn(acc[im][in_][0], acc[im][in_][1]);
                *(__half2*)(Vh + (size_t)(mA + 8) * N + n) =
                    __floats2half2_rn(acc[im][in_][2], acc[im][in_][3]);
            }
        }
        return;
    }

    // RoPE epilogue (Q/K) via smem exchange. Q scale includes log2(e).
    float* sf = (float*)hsm;   // [128][68] fp32 = 34816 B <= 61440 B
    if (wn == 64) {
#pragma unroll
        for (int im = 0; im < 4; im++) {
            int row = wm + im * 16 + gp;
#pragma unroll
            for (int in_ = 0; in_ < 8; in_++) {
                int col = in_ * 8 + 2 * t4;
                sf[row * 68 + col]           = acc[im][in_][0];
                sf[row * 68 + col + 1]       = acc[im][in_][1];
                sf[(row + 8) * 68 + col]     = acc[im][in_][2];
                sf[(row + 8) * 68 + col + 1] = acc[im][in_][3];
            }
        }
    }
    __syncthreads();
    if (wn == 0) {
        const float scale = (z == 0)
            ? 0.08838834764831845f * 1.44269504088896340736f : 1.0f;
        __half* Out = (z == 0) ? Qh : Kh;
#pragma unroll
        for (int im = 0; im < 4; im++) {
            int row = wm + im * 16 + gp;
            int sAi = (m0 + row) & (Sc - 1);
            int sBi = (m0 + row + 8) & (Sc - 1);
#pragma unroll
            for (int in_ = 0; in_ < 8; in_++) {
                int col = in_ * 8 + 2 * t4;
                float2 cA  = *(const float2*)(cosp + sAi * DHc + col);
                float2 snA = *(const float2*)(sinp + sAi * DHc + col);
                float2 cB  = *(const float2*)(cosp + sBi * DHc + col);
                float2 snB = *(const float2*)(sinp + sBi * DHc + col);
                float a0 = acc[im][in_][0], a1 = acc[im][in_][1];
                float a2 = acc[im][in_][2], a3 = acc[im][in_][3];
                float b0 = sf[row * 68 + col],       b1 = sf[row * 68 + col + 1];
                float b2 = sf[(row + 8) * 68 + col], b3 = sf[(row + 8) * 68 + col + 1];
                __half2 loA = __floats2half2_rn(scale * (a0 * cA.x - b0 * snA.x),
                                                scale * (a1 * cA.y - b1 * snA.y));
                __half2 hiA = __floats2half2_rn(scale * (b0 * cA.x + a0 * snA.x),
                                                scale * (b1 * cA.y + a1 * snA.y));
                __half2 loB = __floats2half2_rn(scale * (a2 * cB.x - b2 * snB.x),
                                                scale * (a3 * cB.y - b3 * snB.y));
                __half2 hiB = __floats2half2_rn(scale * (b2 * cB.x + a2 * snB.x),
                                                scale * (b3 * cB.y + a3 * snB.y));
                size_t gr = (size_t)(m0 + row) * Dc + n0 + col;
                *(__half2*)(Out + gr)                      = loA;
                *(__half2*)(Out + gr + 64)                 = hiA;
                *(__half2*)(Out + gr + (size_t)8 * Dc)      = loB;
                *(__half2*)(Out + gr + (size_t)8 * Dc + 64) = hiB;
            }
        }
    }
}

// ---------------------------------------------------------------------------
// O projection GEMM: BM=64, BN=128, 128 thr, warp tile 64x32, 3-stage
// pipeline, 4 CTAs/SM. fp32 out. ysel picks the m-tile half:
// ysel=0 -> y in {0..15, 32..47} (q-blocks 0..15); ysel=1 -> the rest.
// ---------------------------------------------------------------------------
__global__ void __launch_bounds__(128, 4) gemm_o(const __half* __restrict__ A,
                                                 const __half* __restrict__ B,
                                                 float* __restrict__ Cf,
                                                 int M, int N, int K, int ysel) {
    extern __shared__ __half hsm[];

    const int tid  = threadIdx.x;
    const int wid  = tid >> 5;
    const int lane = tid & 31;
    const int wn = wid * 32;
    const int gp = lane >> 2;
    const int t4 = lane & 3;
    const int yy = (blockIdx.y & 15) + (ysel << 4) + ((blockIdx.y >> 4) << 5);
    const int m0 = yy * 64;
    const int n0 = blockIdx.x * 128;

    const int arow = (lane & 7) + ((lane >> 3) & 1) * 8;
    const int acol = (lane >> 4) * 8;
    const int brow = (lane & 7) + (lane >> 4) * 8;
    const int bcol = ((lane >> 3) & 1) * 8;

    const int lrow = tid >> 2;         // 0..31
    const int lseg = tid & 3;
    const __half* Ag = A + (size_t)(m0 + lrow) * K + lseg * 8;
    const __half* Bg = B + (size_t)(n0 + lrow) * K + lseg * 8;

    const uint32_t sS_u = (uint32_t)__cvta_generic_to_shared(hsm);

    auto load_st = [&](int st, int k0) {
        uint32_t bA = sS_u + (uint32_t)(st * GO_STG_H * 2);
        uint32_t bB = bA + (uint32_t)(64 * HST * 2);
#pragma unroll
        for (int p = 0; p < 2; p++) {
            int row = lrow + p * 32;
            CP_ASYNC16(bA + (uint32_t)((row * HST + lseg * 8) * 2),
                       Ag + (size_t)p * 32 * K + k0);
        }
#pragma unroll
        for (int p = 0; p < 4; p++) {
            int row = lrow + p * 32;
            CP_ASYNC16(bB + (uint32_t)((row * HST + lseg * 8) * 2),
                       Bg + (size_t)p * 32 * K + k0);
        }
        asm volatile("cp.async.commit_group;\n");
    };

    float acc[4][4][4];
#pragma unroll
    for (int im = 0; im < 4; im++)
#pragma unroll
        for (int in_ = 0; in_ < 4; in_++)
#pragma unroll
            for (int r = 0; r < 4; r++) acc[im][in_][r] = 0.f;

    const int nt = K / 32;

    load_st(0, 0);
    load_st(1, 32);

    int cs = 0, ld = 2;
    for (int kt = 0; kt < nt; kt++) {
        if (kt + 1 < nt) asm volatile("cp.async.wait_group 1;\n");
        else             asm volatile("cp.async.wait_group 0;\n");
        __syncthreads();

        if (kt + 2 < nt) {
            load_st(ld, (kt + 2) * 32);
            ld = (ld == 2) ? 0 : ld + 1;
        }

        const uint32_t cA_u = sS_u + (uint32_t)(cs * GO_STG_H * 2);
        const uint32_t cB_u = cA_u + (uint32_t)(64 * HST * 2);
        cs = (cs == 2) ? 0 : cs + 1;

#pragma unroll
        for (int ks = 0; ks < 2; ks++) {
            const int kk = ks * 16;
            uint32_t af[4][4];
#pragma unroll
            for (int im = 0; im < 4; im++)
                LDSM_X4(af[im][0], af[im][1], af[im][2], af[im][3],
                        cA_u + (uint32_t)(((im * 16 + arow) * HST + kk + acol) * 2));
            uint32_t bf[4][2];
#pragma unroll
            for (int j2 = 0; j2 < 2; j2++)
                LDSM_X4(bf[2 * j2][0], bf[2 * j2][1],
                        bf[2 * j2 + 1][0], bf[2 * j2 + 1][1],
                        cB_u + (uint32_t)(((wn + j2 * 16 + brow) * HST + kk + bcol) * 2));
#pragma unroll
            for (int im = 0; im < 4; im++)
#pragma unroll
                for (int in_ = 0; in_ < 4; in_++)
                    MMA_F16(acc[im][in_], af[im][0], af[im][1], af[im][2],
                            af[im][3], bf[in_][0], bf[in_][1]);
        }
    }

#pragma unroll
    for (int im = 0; im < 4; im++) {
        const int mA = m0 + im * 16 + gp;
#pragma unroll
        for (int in_ = 0; in_ < 4; in_++) {
            const int n = n0 + wn + in_ * 8 + 2 * t4;
            *(float2*)(Cf + (size_t)mA * N + n) =
                make_float2(acc[im][in_][0], acc[im][in_][1]);
            *(float2*)(Cf + (size_t)(mA + 8) * N + n) =
                make_float2(acc[im][in_][2], acc[im][in_][3]);
        }
    }
}

// ---------------------------------------------------------------------------
// Flash attention: BM=BN=64, 128 thr / 4 warps, fp16 mma, XOR-swizzled smem,
// 3 CTAs/SM, exp2 softmax, skip-rescale, early K prefetch. qb_base selects the
// half: qb = qb_base - blockIdx.x (heavy-first within each half).
// ---------------------------------------------------------------------------
constexpr int OFF_Q  = 0;
constexpr int OFF_K0 = 16384;
constexpr int OFF_K1 = 32768;
constexpr int OFF_V  = 49152;
constexpr int OFF_P  = 65536;
constexpr int FL_SMEM_B = 73728;

__global__ void __launch_bounds__(128, 3) flash_tc(const __half* __restrict__ Q,
                                                   const __half* __restrict__ K,
                                                   const __half* __restrict__ V,
                                                   __half* __restrict__ O,
                                                   int qb_base) {
    extern __shared__ char smraw[];
    char* sPc = smraw + OFF_P;
    const uint32_t sQ_u  = (uint32_t)__cvta_generic_to_shared(smraw + OFF_Q);
    const uint32_t sK0_u = (uint32_t)__cvta_generic_to_shared(smraw + OFF_K0);
    const uint32_t sK1_u = (uint32_t)__cvta_generic_to_shared(smraw + OFF_K1);
    const uint32_t sV_u  = (uint32_t)__cvta_generic_to_shared(smraw + OFF_V);
    const uint32_t sP_u  = (uint32_t)__cvta_generic_to_shared(sPc);

    const int tid  = threadIdx.x;
    const int wid  = tid >> 5;
    const int lane = tid & 31;
    const int gp   = lane >> 2;
    const int t4   = lane & 3;
    const int qb   = qb_base - blockIdx.x;   // heavy blocks first
    const int bh   = blockIdx.y;
    const int b    = bh >> 4;
    const int h    = bh & (Hc - 1);
    const size_t base = ((size_t)b * Sc) * Dc + (size_t)h * DHc;
    const int q0   = qb * 64;
    const int wrow = wid * 16;
    const int r0loc = wrow + gp;
    const int r1loc = r0loc + 8;

    const int arow = (lane & 7) + ((lane >> 3) & 1) * 8;
    const int aseg = lane >> 4;
    const int brow = (lane & 7) + (lane >> 4) * 8;
    const int bseg = (lane >> 3) & 1;
    const int vrow = (lane & 7) + ((lane >> 3) & 1) * 8;
    const int vseg = lane >> 4;

    {
#pragma unroll
        for (int p = 0; p < 8; p++) {
            int idx = tid + p * 128;
            int r = idx >> 4, sg = idx & 15;
            CP_ASYNC16(sQ_u + swz16(r, sg),
                       Q + base + (size_t)(q0 + r) * Dc + sg * 8);
        }
#pragma unroll
        for (int p = 0; p < 8; p++) {
            int idx = tid + p * 128;
            int r = idx >> 4, sg = idx & 15;
            CP_ASYNC16(sK0_u + swz16(r, sg),
                       K + base + (size_t)r * Dc + sg * 8);
        }
        asm volatile("cp.async.commit_group;\n");
#pragma unroll
        for (int p = 0; p < 8; p++) {
            int idx = tid + p * 128;
            int r = idx >> 4, sg = idx & 15;
            CP_ASYNC16(sV_u + swz16(r, sg),
                       V + base + (size_t)r * Dc + sg * 8);
        }
        asm volatile("cp.async.commit_group;\n");
    }

    float o[16][4];
#pragma unroll
    for (int n = 0; n < 16; n++)
#pragma unroll
        for (int r = 0; r < 4; r++) o[n][r] = 0.f;
    float m0 = -1e30f, m1 = -1e30f, l0 = 0.f, l1 = 0.f;

    for (int j = 0; j <= qb; ++j) {
        const uint32_t sKc_u = (j & 1) ? sK1_u : sK0_u;
        const uint32_t sKn_u = (j & 1) ? sK0_u : sK1_u;

        asm volatile("cp.async.wait_group 1;\n");
        __syncthreads();

        if (j < qb) {
            const int k0n = (j + 1) * 64;
#pragma unroll
            for (int p = 0; p < 8; p++) {
                int idx = tid + p * 128;
                int r = idx >> 4, sg = idx & 15;
                CP_ASYNC16(sKn_u + swz16(r, sg),
                           K + base + (size_t)(k0n + r) * Dc + sg * 8);
            }
            asm volatile("cp.async.commit_group;\n");
        }

        float sacc[8][4];
#pragma unroll
        for (int n = 0; n < 8; n++)
#pragma unroll
            for (int r = 0; r < 4; r++) sacc[n][r] = 0.f;

#pragma unroll
        for (int kk8 = 0; kk8 < 8; kk8++) {
            uint32_t a0, a1, a2, a3;
            LDSM_X4(a0, a1, a2, a3,
                    sQ_u + swz16(wrow + arow, kk8 * 2 + aseg));
            uint32_t bf[8][2];
#pragma unroll
            for (int j2 = 0; j2 < 4; j2++)
                LDSM_X4(bf[2 * j2][0], bf[2 * j2][1],
                        bf[2 * j2 + 1][0], bf[2 * j2 + 1][1],
                        sKc_u + swz16(j2 * 16 + brow, kk8 * 2 + bseg));
#pragma unroll
            for (int nt = 0; nt < 8; nt++)
                MMA_F16(sacc[nt], a0, a1, a2, a3, bf[nt][0], bf[nt][1]);
        }

        if (j == qb) {
#pragma unroll
            for (int nt = 0; nt < 8; nt++) {
                int c0 = nt * 8 + 2 * t4;
                if (c0 > r0loc)     sacc[nt][0] = -1e30f;
                if (c0 + 1 > r0loc) sacc[nt][1] = -1e30f;
                if (c0 > r1loc)     sacc[nt][2] = -1e30f;
                if (c0 + 1 > r1loc) sacc[nt][3] = -1e30f;
            }
        }

        float mx0 = -1e30f, mx1 = -1e30f;
#pragma unroll
        for (int nt = 0; nt < 8; nt++) {
            mx0 = fmaxf(mx0, fmaxf(sacc[nt][0], sacc[nt][1]));
            mx1 = fmaxf(mx1, fmaxf(sacc[nt][2], sacc[nt][3]));
        }
        mx0 = fmaxf(mx0, __shfl_xor_sync(0xffffffff, mx0, 1));
        mx0 = fmaxf(mx0, __shfl_xor_sync(0xffffffff, mx0, 2));
        mx1 = fmaxf(mx1, __shfl_xor_sync(0xffffffff, mx1, 1));
        mx1 = fmaxf(mx1, __shfl_xor_sync(0xffffffff, mx1, 2));

        float m0n = fmaxf(m0, mx0);
        float m1n = fmaxf(m1, mx1);
        bool nochg = (m0n == m0) && (m1n == m1);
        if (!__all_sync(0xffffffff, nochg)) {
            float corr0 = exp2f(m0 - m0n);
            float corr1 = exp2f(m1 - m1n);
            l0 *= corr0;
            l1 *= corr1;
#pragma unroll
            for (int nt = 0; nt < 16; nt++) {
                o[nt][0] *= corr0; o[nt][1] *= corr0;
                o[nt][2] *= corr1; o[nt][3] *= corr1;
            }
            m0 = m0n; m1 = m1n;
        }

        float ls0 = 0.f, ls1 = 0.f;
#pragma unroll
        for (int nt = 0; nt < 8; nt++) {
            float p0 = exp2f(sacc[nt][0] - m0);
            float p1 = exp2f(sacc[nt][1] - m0);
            float p2 = exp2f(sacc[nt][2] - m1);
            float p3 = exp2f(sacc[nt][3] - m1);
            ls0 += p0 + p1;
            ls1 += p2 + p3;
            *(__half2*)(sPc + swz8(r0loc, nt) + t4 * 4) = __floats2half2_rn(p0, p1);
            *(__half2*)(sPc + swz8(r1loc, nt) + t4 * 4) = __floats2half2_rn(p2, p3);
        }
        ls0 += __shfl_xor_sync(0xffffffff, ls0, 1);
        ls0 += __shfl_xor_sync(0xffffffff, ls0, 2);
        ls1 += __shfl_xor_sync(0xffffffff, ls1, 1);
        ls1 += __shfl_xor_sync(0xffffffff, ls1, 2);
        l0 += ls0;
        l1 += ls1;

        if (j < qb) asm volatile("cp.async.wait_group 1;\n");
        else        asm volatile("cp.async.wait_group 0;\n");
        __syncthreads();

#pragma unroll
        for (int ks = 0; ks < 4; ks++) {
            const int kk = ks * 16;
            uint32_t a0, a1, a2, a3;
            LDSM_X4(a0, a1, a2, a3,
                    sP_u + swz8(wrow + arow, ks * 2 + aseg));
#pragma unroll
            for (int j2 = 0; j2 < 8; j2++) {
                uint32_t b00, b01, b10, b11;
                LDSM_X4_T(b00, b01, b10, b11,
                          sV_u + swz16(kk + vrow, j2 * 2 + vseg));
                MMA_F16(o[2 * j2],     a0, a1, a2, a3, b00, b01);
                MMA_F16(o[2 * j2 + 1], a0, a1, a2, a3, b10, b11);
            }
        }
        __syncthreads();

        if (j < qb) {
            const int k0n = (j + 1) * 64;
#pragma unroll
            for (int p = 0; p < 8; p++) {
                int idx = tid + p * 128;
                int r = idx >> 4, sg = idx & 15;
                CP_ASYNC16(sV_u + swz16(r, sg),
                           V + base + (size_t)(k0n + r) * Dc + sg * 8);
            }
            asm volatile("cp.async.commit_group;\n");
        }
    }

    float inv0 = 1.0f / l0, inv1 = 1.0f / l1;
    const size_t row0 = base + (size_t)(q0 + r0loc) * Dc;
    const size_t row1 = base + (size_t)(q0 + r1loc) * Dc;
#pragma unroll
    for (int nt = 0; nt < 16; nt++) {
        int c0 = nt * 8 + 2 * t4;
        *(__half2*)(O + row0 + c0) =
            __floats2half2_rn(o[nt][0] * inv0, o[nt][1] * inv0);
        *(__half2*)(O + row1 + c0) =
            __floats2half2_rn(o[nt][2] * inv1, o[nt][3] * inv1);
    }
}

// ---------------------------------------------------------------------------
// Launch: fork-join — light half (qb 0..15 flash + matching O-proj tiles) on
// cudaStreamPerThread, heavy half on the launch stream; joined via events so
// graph capture records the parallel branches.
// ---------------------------------------------------------------------------
extern "C" void kernel_launch(void* const* d_in, const int* in_sizes, int n_in,
                              void* d_out, int out_size) {
    const float* x    = (const float*)d_in[0];
    const float* cosp = (const float*)d_in[1];
    const float* sinp = (const float*)d_in[2];
    const float* Wq   = (const float*)d_in[3];
    const float* Wk   = (const float*)d_in[4];
    const float* Wv   = (const float*)d_in[5];
    const float* Wo   = (const float*)d_in[6];
    float* out = (float*)d_out;

    __half *Vh, *xh, *Qh, *Kh, *Ah, *wqh, *wkh, *wvh, *woh;
    cudaGetSymbolAddress((void**)&Vh, g_Vh);
    cudaGetSymbolAddress((void**)&xh, g_xh);
    cudaGetSymbolAddress((void**)&Qh, g_Qh);
    cudaGetSymbolAddress((void**)&Kh, g_Kh);
    cudaGetSymbolAddress((void**)&Ah, g_Ah);
    cudaGetSymbolAddress((void**)&wqh, g_wqh);
    cudaGetSymbolAddress((void**)&wkh, g_wkh);
    cudaGetSymbolAddress((void**)&wvh, g_wvh);
    cudaGetSymbolAddress((void**)&woh, g_woh);

    cudaFuncSetAttribute(gemm_qkv, cudaFuncAttributeMaxDynamicSharedMemorySize,
                         GEMM_SMEM_B);
    cudaFuncSetAttribute(gemm_o, cudaFuncAttributeMaxDynamicSharedMemorySize,
                         GO_SMEM_B);
    cudaFuncSetAttribute(flash_tc, cudaFuncAttributeMaxDynamicSharedMemorySize,
                         FL_SMEM_B);

    // all fp16 conversions in one launch (4 float4 loads, 2 uint4 stores/thread)
    {
        const int nw = Dc * Dc / 4;          // 1048576 float4 per slice
        dim3 cgrid(nw / 1024, 6);
        cvt_all<<<cgrid, 256>>>(x, Wq, Wk, Wv, Wo,
                                xh, wqh, wkh, wvh, woh, nw);
    }

    // fused QKV projections + RoPE/scale epilogue (3-stage pipeline)
    {
        dim3 qgrid(Dc / 128, Mc / 128, 3);   // (16, 32, 3)
        gemm_qkv<<<qgrid, 128, GEMM_SMEM_B>>>(xh, wqh, wkh, wvh,
                                              Qh, Kh, Vh, cosp, sinp);
    }

    // fork: light chain on per-thread stream, heavy chain on launch stream
    cudaEvent_t eFork, eJoin;
    cudaEventCreateWithFlags(&eFork, cudaEventDisableTiming);
    cudaEventCreateWithFlags(&eJoin, cudaEventDisableTiming);
    cudaEventRecord(eFork, 0);
    cudaStreamWaitEvent(cudaStreamPerThread, eFork, 0);

    // light half: flash qb 0..15, then O-proj tiles for those rows
    flash_tc<<<dim3(16, Bc * Hc), 128, FL_SMEM_B, cudaStreamPerThread>>>(
        Qh, Kh, Vh, Ah, 15);
    gemm_o<<<dim3(16, 32), 128, GO_SMEM_B, cudaStreamPerThread>>>(
        Ah, woh, out, Mc, Dc, Dc, 0);
    cudaEventRecord(eJoin, cudaStreamPerThread);

    // heavy half: flash qb 16..31, then O-proj tiles for those rows
    flash_tc<<<dim3(16, Bc * Hc), 128, FL_SMEM_B>>>(Qh, Kh, Vh, Ah, 31);
    gemm_o<<<dim3(16, 32), 128, GO_SMEM_B>>>(Ah, woh, out, Mc, Dc, Dc, 1);

    // join
    cudaStreamWaitEvent(0, eJoin, 0);
}

// round 17
// speedup vs baseline: 1.0498x; 1.0498x over previous
#include <cuda_runtime.h>
#include <cuda_fp16.h>
#include <math.h>
#include <stdint.h>

// Problem constants
constexpr int Bc  = 2;
constexpr int Sc  = 2048;
constexpr int Dc  = 2048;
constexpr int Hc  = 16;
constexpr int DHc = 128;
constexpr int Mc  = Bc * Sc;   // 4096 rows for projections

// ---------------------------------------------------------------------------
// Scratch (device globals: allocation-free per harness rules)
// ---------------------------------------------------------------------------
__device__ __half g_Vh [(size_t)Mc * Dc];      // half V
__device__ __half g_xh [(size_t)Mc * Dc];
__device__ __half g_Qh [(size_t)Mc * Dc];      // roped + (scale*log2e)-scaled
__device__ __half g_Kh [(size_t)Mc * Dc];      // roped
__device__ __half g_Ah [(size_t)Mc * Dc];      // attention out (half)
__device__ __half g_wqh[(size_t)Dc * Dc];
__device__ __half g_wkh[(size_t)Dc * Dc];
__device__ __half g_wvh[(size_t)Dc * Dc];
__device__ __half g_woh[(size_t)Dc * Dc];

#define CP_ASYNC16(dst, src) \
    asm volatile("cp.async.cg.shared.global [%0], [%1], 16;\n" :: "r"(dst), "l"(src))

#define MMA_F16(c, a0, a1, a2, a3, b0, b1)                                     \
    asm volatile(                                                              \
        "mma.sync.aligned.m16n8k16.row.col.f32.f16.f16.f32 "                   \
        "{%0,%1,%2,%3}, {%4,%5,%6,%7}, {%8,%9}, {%0,%1,%2,%3};\n"              \
        : "+f"((c)[0]), "+f"((c)[1]), "+f"((c)[2]), "+f"((c)[3])               \
        : "r"(a0), "r"(a1), "r"(a2), "r"(a3), "r"(b0), "r"(b1))

#define LDSM_X4(r0, r1, r2, r3, addr)                                          \
    asm volatile("ldmatrix.sync.aligned.m8n8.x4.shared.b16 {%0,%1,%2,%3}, [%4];" \
        : "=r"(r0), "=r"(r1), "=r"(r2), "=r"(r3) : "r"(addr))

#define LDSM_X4_T(r0, r1, r2, r3, addr)                                        \
    asm volatile("ldmatrix.sync.aligned.m8n8.x4.trans.shared.b16 {%0,%1,%2,%3}, [%4];" \
        : "=r"(r0), "=r"(r1), "=r"(r2), "=r"(r3) : "r"(addr))

// 16B-granular XOR swizzles (byte offsets). Row widths: 16 segs (QKV), 8 (P).
__device__ __forceinline__ uint32_t swz16(int row, int seg) {
    return (uint32_t)((row * 16 + (seg ^ (row & 7))) << 4);
}
__device__ __forceinline__ uint32_t swz8(int row, int seg) {
    return (uint32_t)((row * 8 + (seg ^ (row & 7))) << 4);
}

// ---------------------------------------------------------------------------
// fp32 -> fp16: all five inputs, one launch. 4 independent float4 loads per
// thread (MLP=4) arranged as 2 adjacent pairs -> 2 uint4 (16B) stores.
// y<4: weights; y=4,5: x halves. n4 (=1048576) divisible by 1024 exactly.
// ---------------------------------------------------------------------------
__global__ void cvt_all(const float* __restrict__ x,
                        const float* __restrict__ w0, const float* __restrict__ w1,
                        const float* __restrict__ w2, const float* __restrict__ w3,
                        __half* __restrict__ xh,
                        __half* __restrict__ o0, __half* __restrict__ o1,
                        __half* __restrict__ o2, __half* __restrict__ o3, int n4) {
    const float* in;
    __half* out;
    switch (blockIdx.y) {
        case 0:  in = w0; out = o0; break;
        case 1:  in = w1; out = o1; break;
        case 2:  in = w2; out = o2; break;
        case 3:  in = w3; out = o3; break;
        case 4:  in = x;                     out = xh;                     break;
        default: in = x + (size_t)n4 * 4;    out = xh + (size_t)n4 * 4;    break;
    }
    const int base = blockIdx.x * 1024 + threadIdx.x * 2;
    float4 v0 = *(const float4*)(in + (size_t)base * 4);
    float4 v1 = *(const float4*)(in + (size_t)(base + 1) * 4);
    float4 v2 = *(const float4*)(in + (size_t)(base + 512) * 4);
    float4 v3 = *(const float4*)(in + (size_t)(base + 513) * 4);

    uint4 u0, u1;
    __half2 h;
    h = __floats2half2_rn(v0.x, v0.y); u0.x = *(uint32_t*)&h;
    h = __floats2half2_rn(v0.z, v0.w); u0.y = *(uint32_t*)&h;
    h = __floats2half2_rn(v1.x, v1.y); u0.z = *(uint32_t*)&h;
    h = __floats2half2_rn(v1.z, v1.w); u0.w = *(uint32_t*)&h;
    h = __floats2half2_rn(v2.x, v2.y); u1.x = *(uint32_t*)&h;
    h = __floats2half2_rn(v2.z, v2.w); u1.y = *(uint32_t*)&h;
    h = __floats2half2_rn(v3.x, v3.y); u1.z = *(uint32_t*)&h;
    h = __floats2half2_rn(v3.z, v3.w); u1.w = *(uint32_t*)&h;

    *(uint4*)(out + (size_t)base * 4)         = u0;
    *(uint4*)(out + (size_t)(base + 512) * 4) = u1;
}

// ---------------------------------------------------------------------------
// Shared GEMM constants
// ---------------------------------------------------------------------------
constexpr int HST = 40;                          // halves per smem row
constexpr int QKV_STG_H = 256 * HST;             // stage: A 128 + B 128 rows
constexpr int GEMM_SMEM_B = 3 * QKV_STG_H * 2;   // 61440 bytes (3-stage)
constexpr int GO_STG_H = 192 * HST;              // stage: A 64 + B 128 rows
constexpr int GO_SMEM_B = 3 * GO_STG_H * 2;      // 46080 bytes (3-stage)

// ---------------------------------------------------------------------------
// Fused QKV projection: BM=BN=128, BK=32, 128 thr, 3-stage cp.async pipeline
// (loads issued after the barrier into stage (kt+2)%3 — race-free).
// z selects W/output; z<2 fuses RoPE (+ Q scale with log2e folded in).
// ---------------------------------------------------------------------------
__global__ void __launch_bounds__(128, 3) gemm_qkv(
    const __half* __restrict__ A,
    const __half* __restrict__ Bq, const __half* __restrict__ Bk,
    const __half* __restrict__ Bv,
    __half* __restrict__ Qh, __half* __restrict__ Kh, __half* __restrict__ Vh,
    const float* __restrict__ cosp, const float* __restrict__ sinp) {
    extern __shared__ __half hsm[];

    const int z = blockIdx.z;
    const __half* B = (z == 0) ? Bq : ((z == 1) ? Bk : Bv);
    const int K = Dc, N = Dc;

    const int tid  = threadIdx.x;
    const int wid  = tid >> 5;
    const int lane = tid & 31;
    const int wm = (wid & 1) * 64;
    const int wn = (wid >> 1) * 64;
    const int gp = lane >> 2;
    const int t4 = lane & 3;
    const int m0 = blockIdx.y * 128;
    const int n0 = blockIdx.x * 128;

    const int arow = (lane & 7) + ((lane >> 3) & 1) * 8;
    const int acol = (lane >> 4) * 8;
    const int brow = (lane & 7) + (lane >> 4) * 8;
    const int bcol = ((lane >> 3) & 1) * 8;

    const int lrow = tid >> 2;
    const int lseg = tid & 3;
    const __half* Ag = A + (size_t)(m0 + lrow) * K + lseg * 8;
    const __half* Bg = B + (size_t)(n0 + lrow) * K + lseg * 8;

    const uint32_t sS_u = (uint32_t)__cvta_generic_to_shared(hsm);

    auto load_st = [&](int st, int k0) {
        uint32_t bA = sS_u + (uint32_t)(st * QKV_STG_H * 2);
        uint32_t bB = bA + (uint32_t)(128 * HST * 2);
#pragma unroll
        for (int p = 0; p < 4; p++) {
            int row = lrow + p * 32;
            CP_ASYNC16(bA + (uint32_t)((row * HST + lseg * 8) * 2),
                       Ag + (size_t)p * 32 * K + k0);
            CP_ASYNC16(bB + (uint32_t)((row * HST + lseg * 8) * 2),
                       Bg + (size_t)p * 32 * K + k0);
        }
        asm volatile("cp.async.commit_group;\n");
    };

    float acc[4][8][4];
#pragma unroll
    for (int im = 0; im < 4; im++)
#pragma unroll
        for (int in_ = 0; in_ < 8; in_++)
#pragma unroll
            for (int r = 0; r < 4; r++) acc[im][in_][r] = 0.f;

    const int nt = K / 32;

    load_st(0, 0);
    load_st(1, 32);

    int cs = 0, ld = 2;
    for (int kt = 0; kt < nt; kt++) {
        if (kt + 1 < nt) asm volatile("cp.async.wait_group 1;\n");
        else             asm volatile("cp.async.wait_group 0;\n");
        __syncthreads();

        if (kt + 2 < nt) {
            load_st(ld, (kt + 2) * 32);
            ld = (ld == 2) ? 0 : ld + 1;
        }

        const uint32_t cA_u = sS_u + (uint32_t)(cs * QKV_STG_H * 2);
        const uint32_t cB_u = cA_u + (uint32_t)(128 * HST * 2);
        cs = (cs == 2) ? 0 : cs + 1;

#pragma unroll
        for (int ks = 0; ks < 2; ks++) {
            const int kk = ks * 16;
            uint32_t af[4][4];
#pragma unroll
            for (int im = 0; im < 4; im++)
                LDSM_X4(af[im][0], af[im][1], af[im][2], af[im][3],
                        cA_u + (uint32_t)(((wm + im * 16 + arow) * HST + kk + acol) * 2));
            uint32_t bf[8][2];
#pragma unroll
            for (int j2 = 0; j2 < 4; j2++)
                LDSM_X4(bf[2 * j2][0], bf[2 * j2][1],
                        bf[2 * j2 + 1][0], bf[2 * j2 + 1][1],
                        cB_u + (uint32_t)(((wn + j2 * 16 + brow) * HST + kk + bcol) * 2));
#pragma unroll
            for (int im = 0; im < 4; im++)
#pragma unroll
                for (int in_ = 0; in_ < 8; in_++)
                    MMA_F16(acc[im][in_], af[im][0], af[im][1], af[im][2],
                            af[im][3], bf[in_][0], bf[in_][1]);
        }
    }
    __syncthreads();   // done with smem before epilogue reuses it

    if (z == 2) {
#pragma unroll
        for (int im = 0; im < 4; im++) {
            const int mA = m0 + wm + im * 16 + gp;
#pragma unroll
            for (int in_ = 0; in_ < 8; in_++) {
                const int n = n0 + wn + in_ * 8 + 2 * t4;
                *(__half2*)(Vh + (size_t)mA * N + n) =
                    __floats2half2_rn(acc[im][in_][0], acc[im][in_][1]);
                *(__half2*)(Vh + (size_t)(mA + 8) * N + n) =
                    __floats2half2_rn(acc[im][in_][2], acc[im][in_][3]);
            }
        }
        return;
    }

    // RoPE epilogue (Q/K) via smem exchange. Q scale includes log2(e).
    float* sf = (float*)hsm;   // [128][68] fp32 = 34816 B <= 61440 B
    if (wn == 64) {
#pragma unroll
        for (int im = 0; im < 4; im++) {
            int row = wm + im * 16 + gp;
#pragma unroll
            for (int in_ = 0; in_ < 8; in_++) {
                int col = in_ * 8 + 2 * t4;
                sf[row * 68 + col]           = acc[im][in_][0];
                sf[row * 68 + col + 1]       = acc[im][in_][1];
                sf[(row + 8) * 68 + col]     = acc[im][in_][2];
                sf[(row + 8) * 68 + col + 1] = acc[im][in_][3];
            }
        }
    }
    __syncthreads();
    if (wn == 0) {
        const float scale = (z == 0)
            ? 0.08838834764831845f * 1.44269504088896340736f : 1.0f;
        __half* Out = (z == 0) ? Qh : Kh;
#pragma unroll
        for (int im = 0; im < 4; im++) {
            int row = wm + im * 16 + gp;
            int sAi = (m0 + row) & (Sc - 1);
            int sBi = (m0 + row + 8) & (Sc - 1);
#pragma unroll
            for (int in_ = 0; in_ < 8; in_++) {
                int col = in_ * 8 + 2 * t4;
                float2 cA  = *(const float2*)(cosp + sAi * DHc + col);
                float2 snA = *(const float2*)(sinp + sAi * DHc + col);
                float2 cB  = *(const float2*)(cosp + sBi * DHc + col);
                float2 snB = *(const float2*)(sinp + sBi * DHc + col);
                float a0 = acc[im][in_][0], a1 = acc[im][in_][1];
                float a2 = acc[im][in_][2], a3 = acc[im][in_][3];
                float b0 = sf[row * 68 + col],       b1 = sf[row * 68 + col + 1];
                float b2 = sf[(row + 8) * 68 + col], b3 = sf[(row + 8) * 68 + col + 1];
                __half2 loA = __floats2half2_rn(scale * (a0 * cA.x - b0 * snA.x),
                                                scale * (a1 * cA.y - b1 * snA.y));
                __half2 hiA = __floats2half2_rn(scale * (b0 * cA.x + a0 * snA.x),
                                                scale * (b1 * cA.y + a1 * snA.y));
                __half2 loB = __floats2half2_rn(scale * (a2 * cB.x - b2 * snB.x),
                                                scale * (a3 * cB.y - b3 * snB.y));
                __half2 hiB = __floats2half2_rn(scale * (b2 * cB.x + a2 * snB.x),
                                                scale * (b3 * cB.y + a3 * snB.y));
                size_t gr = (size_t)(m0 + row) * Dc + n0 + col;
                *(__half2*)(Out + gr)                      = loA;
                *(__half2*)(Out + gr + 64)                 = hiA;
                *(__half2*)(Out + gr + (size_t)8 * Dc)      = loB;
                *(__half2*)(Out + gr + (size_t)8 * Dc + 64) = hiB;
            }
        }
    }
}

// ---------------------------------------------------------------------------
// O projection GEMM: BM=64, BN=128, 128 thr, warp tile 64x32, 3-stage
// pipeline, 4 CTAs/SM. fp32 out. (Round-15 proven shape, unsplit.)
// ---------------------------------------------------------------------------
__global__ void __launch_bounds__(128, 4) gemm_o(const __half* __restrict__ A,
                                                 const __half* __restrict__ B,
                                                 float* __restrict__ Cf,
                                                 int M, int N, int K) {
    extern __shared__ __half hsm[];

    const int tid  = threadIdx.x;
    const int wid  = tid >> 5;
    const int lane = tid & 31;
    const int wn = wid * 32;
    const int gp = lane >> 2;
    const int t4 = lane & 3;
    const int m0 = blockIdx.y * 64;
    const int n0 = blockIdx.x * 128;

    const int arow = (lane & 7) + ((lane >> 3) & 1) * 8;
    const int acol = (lane >> 4) * 8;
    const int brow = (lane & 7) + (lane >> 4) * 8;
    const int bcol = ((lane >> 3) & 1) * 8;

    const int lrow = tid >> 2;         // 0..31
    const int lseg = tid & 3;
    const __half* Ag = A + (size_t)(m0 + lrow) * K + lseg * 8;
    const __half* Bg = B + (size_t)(n0 + lrow) * K + lseg * 8;

    const uint32_t sS_u = (uint32_t)__cvta_generic_to_shared(hsm);

    auto load_st = [&](int st, int k0) {
        uint32_t bA = sS_u + (uint32_t)(st * GO_STG_H * 2);
        uint32_t bB = bA + (uint32_t)(64 * HST * 2);
#pragma unroll
        for (int p = 0; p < 2; p++) {
            int row = lrow + p * 32;
            CP_ASYNC16(bA + (uint32_t)((row * HST + lseg * 8) * 2),
                       Ag + (size_t)p * 32 * K + k0);
        }
#pragma unroll
        for (int p = 0; p < 4; p++) {
            int row = lrow + p * 32;
            CP_ASYNC16(bB + (uint32_t)((row * HST + lseg * 8) * 2),
                       Bg + (size_t)p * 32 * K + k0);
        }
        asm volatile("cp.async.commit_group;\n");
    };

    float acc[4][4][4];
#pragma unroll
    for (int im = 0; im < 4; im++)
#pragma unroll
        for (int in_ = 0; in_ < 4; in_++)
#pragma unroll
            for (int r = 0; r < 4; r++) acc[im][in_][r] = 0.f;

    const int nt = K / 32;

    load_st(0, 0);
    load_st(1, 32);

    int cs = 0, ld = 2;
    for (int kt = 0; kt < nt; kt++) {
        if (kt + 1 < nt) asm volatile("cp.async.wait_group 1;\n");
        else             asm volatile("cp.async.wait_group 0;\n");
        __syncthreads();

        if (kt + 2 < nt) {
            load_st(ld, (kt + 2) * 32);
            ld = (ld == 2) ? 0 : ld + 1;
        }

        const uint32_t cA_u = sS_u + (uint32_t)(cs * GO_STG_H * 2);
        const uint32_t cB_u = cA_u + (uint32_t)(64 * HST * 2);
        cs = (cs == 2) ? 0 : cs + 1;

#pragma unroll
        for (int ks = 0; ks < 2; ks++) {
            const int kk = ks * 16;
            uint32_t af[4][4];
#pragma unroll
            for (int im = 0; im < 4; im++)
                LDSM_X4(af[im][0], af[im][1], af[im][2], af[im][3],
                        cA_u + (uint32_t)(((im * 16 + arow) * HST + kk + acol) * 2));
            uint32_t bf[4][2];
#pragma unroll
            for (int j2 = 0; j2 < 2; j2++)
                LDSM_X4(bf[2 * j2][0], bf[2 * j2][1],
                        bf[2 * j2 + 1][0], bf[2 * j2 + 1][1],
                        cB_u + (uint32_t)(((wn + j2 * 16 + brow) * HST + kk + bcol) * 2));
#pragma unroll
            for (int im = 0; im < 4; im++)
#pragma unroll
                for (int in_ = 0; in_ < 4; in_++)
                    MMA_F16(acc[im][in_], af[im][0], af[im][1], af[im][2],
                            af[im][3], bf[in_][0], bf[in_][1]);
        }
    }

#pragma unroll
    for (int im = 0; im < 4; im++) {
        const int mA = m0 + im * 16 + gp;
#pragma unroll
        for (int in_ = 0; in_ < 4; in_++) {
            const int n = n0 + wn + in_ * 8 + 2 * t4;
            *(float2*)(Cf + (size_t)mA * N + n) =
                make_float2(acc[im][in_][0], acc[im][in_][1]);
            *(float2*)(Cf + (size_t)(mA + 8) * N + n) =
                make_float2(acc[im][in_][2], acc[im][in_][3]);
        }
    }
}

// ---------------------------------------------------------------------------
// Flash attention: BM=BN=64, 128 thr / 4 warps, fp16 mma, XOR-swizzled smem,
// 3 CTAs/SM, exp2 softmax, skip-rescale, early K prefetch, heavy-first.
// (Round-15 proven shape, unsplit.)
// ---------------------------------------------------------------------------
constexpr int OFF_Q  = 0;
constexpr int OFF_K0 = 16384;
constexpr int OFF_K1 = 32768;
constexpr int OFF_V  = 49152;
constexpr int OFF_P  = 65536;
constexpr int FL_SMEM_B = 73728;

__global__ void __launch_bounds__(128, 3) flash_tc(const __half* __restrict__ Q,
                                                   const __half* __restrict__ K,
                                                   const __half* __restrict__ V,
                                                   __half* __restrict__ O) {
    extern __shared__ char smraw[];
    char* sPc = smraw + OFF_P;
    const uint32_t sQ_u  = (uint32_t)__cvta_generic_to_shared(smraw + OFF_Q);
    const uint32_t sK0_u = (uint32_t)__cvta_generic_to_shared(smraw + OFF_K0);
    const uint32_t sK1_u = (uint32_t)__cvta_generic_to_shared(smraw + OFF_K1);
    const uint32_t sV_u  = (uint32_t)__cvta_generic_to_shared(smraw + OFF_V);
    const uint32_t sP_u  = (uint32_t)__cvta_generic_to_shared(sPc);

    const int tid  = threadIdx.x;
    const int wid  = tid >> 5;
    const int lane = tid & 31;
    const int gp   = lane >> 2;
    const int t4   = lane & 3;
    const int qb   = gridDim.x - 1 - blockIdx.x;   // heavy blocks first
    const int bh   = blockIdx.y;
    const int b    = bh >> 4;
    const int h    = bh & (Hc - 1);
    const size_t base = ((size_t)b * Sc) * Dc + (size_t)h * DHc;
    const int q0   = qb * 64;
    const int wrow = wid * 16;
    const int r0loc = wrow + gp;
    const int r1loc = r0loc + 8;

    const int arow = (lane & 7) + ((lane >> 3) & 1) * 8;
    const int aseg = lane >> 4;
    const int brow = (lane & 7) + (lane >> 4) * 8;
    const int bseg = (lane >> 3) & 1;
    const int vrow = (lane & 7) + ((lane >> 3) & 1) * 8;
    const int vseg = lane >> 4;

    {
#pragma unroll
        for (int p = 0; p < 8; p++) {
            int idx = tid + p * 128;
            int r = idx >> 4, sg = idx & 15;
            CP_ASYNC16(sQ_u + swz16(r, sg),
                       Q + base + (size_t)(q0 + r) * Dc + sg * 8);
        }
#pragma unroll
        for (int p = 0; p < 8; p++) {
            int idx = tid + p * 128;
            int r = idx >> 4, sg = idx & 15;
            CP_ASYNC16(sK0_u + swz16(r, sg),
                       K + base + (size_t)r * Dc + sg * 8);
        }
        asm volatile("cp.async.commit_group;\n");
#pragma unroll
        for (int p = 0; p < 8; p++) {
            int idx = tid + p * 128;
            int r = idx >> 4, sg = idx & 15;
            CP_ASYNC16(sV_u + swz16(r, sg),
                       V + base + (size_t)r * Dc + sg * 8);
        }
        asm volatile("cp.async.commit_group;\n");
    }

    float o[16][4];
#pragma unroll
    for (int n = 0; n < 16; n++)
#pragma unroll
        for (int r = 0; r < 4; r++) o[n][r] = 0.f;
    float m0 = -1e30f, m1 = -1e30f, l0 = 0.f, l1 = 0.f;

    for (int j = 0; j <= qb; ++j) {
        const uint32_t sKc_u = (j & 1) ? sK1_u : sK0_u;
        const uint32_t sKn_u = (j & 1) ? sK0_u : sK1_u;

        asm volatile("cp.async.wait_group 1;\n");
        __syncthreads();

        if (j < qb) {
            const int k0n = (j + 1) * 64;
#pragma unroll
            for (int p = 0; p < 8; p++) {
                int idx = tid + p * 128;
                int r = idx >> 4, sg = idx & 15;
                CP_ASYNC16(sKn_u + swz16(r, sg),
                           K + base + (size_t)(k0n + r) * Dc + sg * 8);
            }
            asm volatile("cp.async.commit_group;\n");
        }

        float sacc[8][4];
#pragma unroll
        for (int n = 0; n < 8; n++)
#pragma unroll
            for (int r = 0; r < 4; r++) sacc[n][r] = 0.f;

#pragma unroll
        for (int kk8 = 0; kk8 < 8; kk8++) {
            uint32_t a0, a1, a2, a3;
            LDSM_X4(a0, a1, a2, a3,
                    sQ_u + swz16(wrow + arow, kk8 * 2 + aseg));
            uint32_t bf[8][2];
#pragma unroll
            for (int j2 = 0; j2 < 4; j2++)
                LDSM_X4(bf[2 * j2][0], bf[2 * j2][1],
                        bf[2 * j2 + 1][0], bf[2 * j2 + 1][1],
                        sKc_u + swz16(j2 * 16 + brow, kk8 * 2 + bseg));
#pragma unroll
            for (int nt = 0; nt < 8; nt++)
                MMA_F16(sacc[nt], a0, a1, a2, a3, bf[nt][0], bf[nt][1]);
        }

        if (j == qb) {
#pragma unroll
            for (int nt = 0; nt < 8; nt++) {
                int c0 = nt * 8 + 2 * t4;
                if (c0 > r0loc)     sacc[nt][0] = -1e30f;
                if (c0 + 1 > r0loc) sacc[nt][1] = -1e30f;
                if (c0 > r1loc)     sacc[nt][2] = -1e30f;
                if (c0 + 1 > r1loc) sacc[nt][3] = -1e30f;
            }
        }

        float mx0 = -1e30f, mx1 = -1e30f;
#pragma unroll
        for (int nt = 0; nt < 8; nt++) {
            mx0 = fmaxf(mx0, fmaxf(sacc[nt][0], sacc[nt][1]));
            mx1 = fmaxf(mx1, fmaxf(sacc[nt][2], sacc[nt][3]));
        }
        mx0 = fmaxf(mx0, __shfl_xor_sync(0xffffffff, mx0, 1));
        mx0 = fmaxf(mx0, __shfl_xor_sync(0xffffffff, mx0, 2));
        mx1 = fmaxf(mx1, __shfl_xor_sync(0xffffffff, mx1, 1));
        mx1 = fmaxf(mx1, __shfl_xor_sync(0xffffffff, mx1, 2));

        float m0n = fmaxf(m0, mx0);
        float m1n = fmaxf(m1, mx1);
        bool nochg = (m0n == m0) && (m1n == m1);
        if (!__all_sync(0xffffffff, nochg)) {
            float corr0 = exp2f(m0 - m0n);
            float corr1 = exp2f(m1 - m1n);
            l0 *= corr0;
            l1 *= corr1;
#pragma unroll
            for (int nt = 0; nt < 16; nt++) {
                o[nt][0] *= corr0; o[nt][1] *= corr0;
                o[nt][2] *= corr1; o[nt][3] *= corr1;
            }
            m0 = m0n; m1 = m1n;
        }

        float ls0 = 0.f, ls1 = 0.f;
#pragma unroll
        for (int nt = 0; nt < 8; nt++) {
            float p0 = exp2f(sacc[nt][0] - m0);
            float p1 = exp2f(sacc[nt][1] - m0);
            float p2 = exp2f(sacc[nt][2] - m1);
            float p3 = exp2f(sacc[nt][3] - m1);
            ls0 += p0 + p1;
            ls1 += p2 + p3;
            *(__half2*)(sPc + swz8(r0loc, nt) + t4 * 4) = __floats2half2_rn(p0, p1);
            *(__half2*)(sPc + swz8(r1loc, nt) + t4 * 4) = __floats2half2_rn(p2, p3);
        }
        ls0 += __shfl_xor_sync(0xffffffff, ls0, 1);
        ls0 += __shfl_xor_sync(0xffffffff, ls0, 2);
        ls1 += __shfl_xor_sync(0xffffffff, ls1, 1);
        ls1 += __shfl_xor_sync(0xffffffff, ls1, 2);
        l0 += ls0;
        l1 += ls1;

        if (j < qb) asm volatile("cp.async.wait_group 1;\n");
        else        asm volatile("cp.async.wait_group 0;\n");
        __syncthreads();

#pragma unroll
        for (int ks = 0; ks < 4; ks++) {
            const int kk = ks * 16;
            uint32_t a0, a1, a2, a3;
            LDSM_X4(a0, a1, a2, a3,
                    sP_u + swz8(wrow + arow, ks * 2 + aseg));
#pragma unroll
            for (int j2 = 0; j2 < 8; j2++) {
                uint32_t b00, b01, b10, b11;
                LDSM_X4_T(b00, b01, b10, b11,
                          sV_u + swz16(kk + vrow, j2 * 2 + vseg));
                MMA_F16(o[2 * j2],     a0, a1, a2, a3, b00, b01);
                MMA_F16(o[2 * j2 + 1], a0, a1, a2, a3, b10, b11);
            }
        }
        __syncthreads();

        if (j < qb) {
            const int k0n = (j + 1) * 64;
#pragma unroll
            for (int p = 0; p < 8; p++) {
                int idx = tid + p * 128;
                int r = idx >> 4, sg = idx & 15;
                CP_ASYNC16(sV_u + swz16(r, sg),
                           V + base + (size_t)(k0n + r) * Dc + sg * 8);
            }
            asm volatile("cp.async.commit_group;\n");
        }
    }

    float inv0 = 1.0f / l0, inv1 = 1.0f / l1;
    const size_t row0 = base + (size_t)(q0 + r0loc) * Dc;
    const size_t row1 = base + (size_t)(q0 + r1loc) * Dc;
#pragma unroll
    for (int nt = 0; nt < 16; nt++) {
        int c0 = nt * 8 + 2 * t4;
        *(__half2*)(O + row0 + c0) =
            __floats2half2_rn(o[nt][0] * inv0, o[nt][1] * inv0);
        *(__half2*)(O + row1 + c0) =
            __floats2half2_rn(o[nt][2] * inv1, o[nt][3] * inv1);
    }
}

// ---------------------------------------------------------------------------
// Launch (round-15 proven serial structure)
// ---------------------------------------------------------------------------
extern "C" void kernel_launch(void* const* d_in, const int* in_sizes, int n_in,
                              void* d_out, int out_size) {
    const float* x    = (const float*)d_in[0];
    const float* cosp = (const float*)d_in[1];
    const float* sinp = (const float*)d_in[2];
    const float* Wq   = (const float*)d_in[3];
    const float* Wk   = (const float*)d_in[4];
    const float* Wv   = (const float*)d_in[5];
    const float* Wo   = (const float*)d_in[6];
    float* out = (float*)d_out;

    __half *Vh, *xh, *Qh, *Kh, *Ah, *wqh, *wkh, *wvh, *woh;
    cudaGetSymbolAddress((void**)&Vh, g_Vh);
    cudaGetSymbolAddress((void**)&xh, g_xh);
    cudaGetSymbolAddress((void**)&Qh, g_Qh);
    cudaGetSymbolAddress((void**)&Kh, g_Kh);
    cudaGetSymbolAddress((void**)&Ah, g_Ah);
    cudaGetSymbolAddress((void**)&wqh, g_wqh);
    cudaGetSymbolAddress((void**)&wkh, g_wkh);
    cudaGetSymbolAddress((void**)&wvh, g_wvh);
    cudaGetSymbolAddress((void**)&woh, g_woh);

    cudaFuncSetAttribute(gemm_qkv, cudaFuncAttributeMaxDynamicSharedMemorySize,
                         GEMM_SMEM_B);
    cudaFuncSetAttribute(gemm_o, cudaFuncAttributeMaxDynamicSharedMemorySize,
                         GO_SMEM_B);
    cudaFuncSetAttribute(flash_tc, cudaFuncAttributeMaxDynamicSharedMemorySize,
                         FL_SMEM_B);

    // all fp16 conversions in one launch (4 float4 loads, 2 uint4 stores/thread)
    {
        const int nw = Dc * Dc / 4;          // 1048576 float4 per slice
        dim3 cgrid(nw / 1024, 6);
        cvt_all<<<cgrid, 256>>>(x, Wq, Wk, Wv, Wo,
                                xh, wqh, wkh, wvh, woh, nw);
    }

    // fused QKV projections + RoPE/scale epilogue (3-stage pipeline)
    {
        dim3 qgrid(Dc / 128, Mc / 128, 3);   // (16, 32, 3)
        gemm_qkv<<<qgrid, 128, GEMM_SMEM_B>>>(xh, wqh, wkh, wvh,
                                              Qh, Kh, Vh, cosp, sinp);
    }

    // flash attention (heavy-first)
    {
        dim3 fgrid(Sc / 64, Bc * Hc);   // (32, 32)
        flash_tc<<<fgrid, 128, FL_SMEM_B>>>(Qh, Kh, Vh, Ah);
    }

    // O projection (3-stage pipeline, fp32 out)
    {
        dim3 ggrid(Dc / 128, Mc / 64);   // (16, 64)
        gemm_o<<<ggrid, 128, GO_SMEM_B>>>(Ah, woh, out, Mc, Dc, Dc);
    }
}